// round 2
// baseline (speedup 1.0000x reference)
#include <cuda_runtime.h>
#include <math.h>

#define NN 100000
#define NE 1200000
#define D  64
#define NG 512

// -------- scratch (device globals; no allocation) --------
static __device__ float g_h1 [NN * D];   // conv1 output
static __device__ float g_h2 [NN * D];   // conv2 output
static __device__ float g_ns [NN];
static __device__ float g_nd [NN];
static __device__ int   g_dego[NN];
static __device__ int   g_degi[NN];
static __device__ int   g_off [NN + 1];  // CSR offsets (by dst)
static __device__ int   g_cur [NN];      // fill cursors
static __device__ int   g_csrc[NE];      // src node per bucketed edge

// -------- init --------
__global__ void k_zero() {
    int i = blockIdx.x * blockDim.x + threadIdx.x;
    if (i < NN) { g_dego[i] = 0; g_degi[i] = 0; }
}

// -------- degrees --------
__global__ void k_deg(const int* __restrict__ src, const int* __restrict__ dst) {
    int e = blockIdx.x * blockDim.x + threadIdx.x;
    if (e < NE) {
        atomicAdd(&g_dego[src[e]], 1);
        atomicAdd(&g_degi[dst[e]], 1);
    }
}

__global__ void k_norm() {
    int i = blockIdx.x * blockDim.x + threadIdx.x;
    if (i < NN) {
        int dov = g_dego[i]; if (dov < 1) dov = 1;
        int div_ = g_degi[i]; if (div_ < 1) div_ = 1;
        g_ns[i] = rsqrtf((float)dov);
        g_nd[i] = rsqrtf((float)div_);
    }
}

// -------- exclusive prefix scan of degi -> g_off (single block) --------
__global__ void k_scan() {
    __shared__ int part[256];
    const int CH = (NN + 255) / 256;
    int t = threadIdx.x;
    int lo = t * CH;
    int hi = lo + CH; if (hi > NN) hi = NN;
    int s = 0;
    for (int i = lo; i < hi; i++) s += g_degi[i];
    part[t] = s;
    __syncthreads();
    for (int o = 1; o < 256; o <<= 1) {
        int v = (t >= o) ? part[t - o] : 0;
        __syncthreads();
        part[t] += v;
        __syncthreads();
    }
    int base = t ? part[t - 1] : 0;
    for (int i = lo; i < hi; i++) {
        g_off[i] = base;
        g_cur[i] = base;
        base += g_degi[i];
    }
    if (t == 255) g_off[NN] = base;
}

// -------- bucket edges by dst --------
__global__ void k_fill(const int* __restrict__ src, const int* __restrict__ dst) {
    int e = blockIdx.x * blockDim.x + threadIdx.x;
    if (e < NE) {
        int d = dst[e];
        int p = atomicAdd(&g_cur[d], 1);
        g_csrc[p] = src[e];
    }
}

// -------- fused conv: gather-sum + (·nd) @ W + b, LN, ReLU --------
__global__ void k_conv(const float* __restrict__ x, float* __restrict__ y,
                       const float* __restrict__ W, const float* __restrict__ b,
                       const float* __restrict__ gm, const float* __restrict__ bt) {
    __shared__ float Ws[64 * 64];
    int tid = threadIdx.x;
    for (int i = tid; i < 64 * 64; i += blockDim.x) Ws[i] = W[i];
    __syncthreads();

    int lane  = tid & 31;
    int wid   = tid >> 5;
    int nwarp = (gridDim.x * blockDim.x) >> 5;

    for (int n = blockIdx.x * (blockDim.x >> 5) + wid; n < NN; n += nwarp) {
        int off = g_off[n];
        int end = g_off[n + 1];
        float acc0 = 0.f, acc1 = 0.f;
        #pragma unroll 4
        for (int e = off; e < end; e++) {
            int s = __ldg(&g_csrc[e]);
            float nsv = __ldg(&g_ns[s]);
            acc0 += __ldg(&x[s * 64 + lane])      * nsv;
            acc1 += __ldg(&x[s * 64 + 32 + lane]) * nsv;
        }
        float ndv = g_nd[n];
        float a0 = acc0 * ndv;
        float a1 = acc1 * ndv;

        float r0 = b[lane];
        float r1 = b[lane + 32];
        #pragma unroll
        for (int k = 0; k < 32; k++) {
            float xk = __shfl_sync(0xffffffffu, a0, k);
            r0 += xk * Ws[k * 64 + lane];
            r1 += xk * Ws[k * 64 + 32 + lane];
        }
        #pragma unroll
        for (int k = 0; k < 32; k++) {
            float xk = __shfl_sync(0xffffffffu, a1, k);
            r0 += xk * Ws[(k + 32) * 64 + lane];
            r1 += xk * Ws[(k + 32) * 64 + 32 + lane];
        }
        // LayerNorm over 64 (2 vals/lane) + ReLU
        float s = r0 + r1;
        #pragma unroll
        for (int o = 16; o; o >>= 1) s += __shfl_xor_sync(0xffffffffu, s, o);
        float mean = s * (1.f / 64.f);
        float d0 = r0 - mean, d1 = r1 - mean;
        float vv = d0 * d0 + d1 * d1;
        #pragma unroll
        for (int o = 16; o; o >>= 1) vv += __shfl_xor_sync(0xffffffffu, vv, o);
        float inv = rsqrtf(vv * (1.f / 64.f) + 1e-5f);
        float y0 = d0 * inv * gm[lane]      + bt[lane];
        float y1 = d1 * inv * gm[lane + 32] + bt[lane + 32];
        y[n * 64 + lane]      = fmaxf(y0, 0.f);
        y[n * 64 + 32 + lane] = fmaxf(y1, 0.f);
    }
}

// -------- fused pool (sorted graph_ids, binary search) + classifier head --------
__global__ void k_poolcls(const int* __restrict__ gid,
                          const float* __restrict__ Wc1, const float* __restrict__ bc1,
                          const float* __restrict__ g3,  const float* __restrict__ be3,
                          const float* __restrict__ Wc2, const float* __restrict__ bc2,
                          const float* __restrict__ g4,  const float* __restrict__ be4,
                          const float* __restrict__ Wc3, const float* __restrict__ bc3,
                          float* __restrict__ out) {
    __shared__ float hA[64], hB[64], o1[64], red[64];
    int g = blockIdx.x, t = threadIdx.x;

    // binary search node range for graph g (gid sorted)
    int lo = 0, hi = NN;
    while (lo < hi) { int mid = (lo + hi) >> 1; if (__ldg(&gid[mid]) < g)     lo = mid + 1; else hi = mid; }
    int start = lo;
    lo = start; hi = NN;
    while (lo < hi) { int mid = (lo + hi) >> 1; if (__ldg(&gid[mid]) < g + 1) lo = mid + 1; else hi = mid; }
    int end = lo;

    float s = 0.f, m = 0.f;   // post-ReLU values >= 0, so max init 0 is safe
    for (int n = start; n < end; n++) {
        float v = g_h2[n * 64 + t];
        s += v;
        m = fmaxf(m, v);
    }
    float cnt = (float)(end - start); if (cnt < 1.f) cnt = 1.f;
    float mv = s / cnt;
    float xv = m;

    // l2 norm of mean vec
    red[t] = mv * mv; __syncthreads();
    for (int o = 32; o; o >>= 1) { if (t < o) red[t] += red[t + o]; __syncthreads(); }
    float nA = fmaxf(sqrtf(red[0]), 1e-12f); __syncthreads();
    // l2 norm of max vec
    red[t] = xv * xv; __syncthreads();
    for (int o = 32; o; o >>= 1) { if (t < o) red[t] += red[t + o]; __syncthreads(); }
    float nB = fmaxf(sqrtf(red[0]), 1e-12f); __syncthreads();

    hA[t] = mv / nA;
    hB[t] = xv / nB;
    __syncthreads();

    // layer 1: [128] @ Wc1[128,64]
    float acc = bc1[t];
    #pragma unroll 4
    for (int k = 0; k < 64; k++) acc += hA[k] * Wc1[k * 64 + t];
    #pragma unroll 4
    for (int k = 0; k < 64; k++) acc += hB[k] * Wc1[(64 + k) * 64 + t];
    red[t] = acc; __syncthreads();
    for (int o = 32; o; o >>= 1) { if (t < o) red[t] += red[t + o]; __syncthreads(); }
    float mean = red[0] * (1.f / 64.f); __syncthreads();
    float dv = acc - mean;
    red[t] = dv * dv; __syncthreads();
    for (int o = 32; o; o >>= 1) { if (t < o) red[t] += red[t + o]; __syncthreads(); }
    float inv = rsqrtf(red[0] * (1.f / 64.f) + 1e-5f); __syncthreads();
    o1[t] = fmaxf(dv * inv * g3[t] + be3[t], 0.f);
    __syncthreads();

    // layer 2: [64] @ Wc2[64,64]
    acc = bc2[t];
    #pragma unroll 4
    for (int k = 0; k < 64; k++) acc += o1[k] * Wc2[k * 64 + t];
    red[t] = acc; __syncthreads();
    for (int o = 32; o; o >>= 1) { if (t < o) red[t] += red[t + o]; __syncthreads(); }
    mean = red[0] * (1.f / 64.f); __syncthreads();
    dv = acc - mean;
    red[t] = dv * dv; __syncthreads();
    for (int o = 32; o; o >>= 1) { if (t < o) red[t] += red[t + o]; __syncthreads(); }
    inv = rsqrtf(red[0] * (1.f / 64.f) + 1e-5f); __syncthreads();
    float o2 = fmaxf(dv * inv * g4[t] + be4[t], 0.f);

    // layer 3: [64] @ Wc3[64,1]
    red[t] = o2 * Wc3[t]; __syncthreads();
    for (int o = 32; o; o >>= 1) { if (t < o) red[t] += red[t + o]; __syncthreads(); }
    if (t == 0) out[g] = red[0] + bc3[0];
}

extern "C" void kernel_launch(void* const* d_in, const int* in_sizes, int n_in,
                              void* d_out, int out_size) {
    const float* h   = (const float*)d_in[0];
    const int*   src = (const int*)  d_in[1];
    const int*   dst = (const int*)  d_in[2];
    const int*   gid = (const int*)  d_in[3];
    const float* W1  = (const float*)d_in[4];
    const float* b1  = (const float*)d_in[5];
    const float* W2  = (const float*)d_in[6];
    const float* b2  = (const float*)d_in[7];
    const float* g1  = (const float*)d_in[8];
    const float* be1 = (const float*)d_in[9];
    const float* g2  = (const float*)d_in[10];
    const float* be2 = (const float*)d_in[11];
    const float* g3  = (const float*)d_in[12];
    const float* be3 = (const float*)d_in[13];
    const float* g4  = (const float*)d_in[14];
    const float* be4 = (const float*)d_in[15];
    const float* Wc1 = (const float*)d_in[16];
    const float* bc1 = (const float*)d_in[17];
    const float* Wc2 = (const float*)d_in[18];
    const float* bc2 = (const float*)d_in[19];
    const float* Wc3 = (const float*)d_in[20];
    const float* bc3 = (const float*)d_in[21];
    float* out = (float*)d_out;

    float* h1 = nullptr; float* h2 = nullptr;
    cudaGetSymbolAddress((void**)&h1, g_h1);
    cudaGetSymbolAddress((void**)&h2, g_h2);

    k_zero<<<(NN + 255) / 256, 256>>>();
    k_deg <<<(NE + 255) / 256, 256>>>(src, dst);
    k_norm<<<(NN + 255) / 256, 256>>>();
    k_scan<<<1, 256>>>();
    k_fill<<<(NE + 255) / 256, 256>>>(src, dst);

    k_conv<<<1184, 256>>>(h,  h1, W1, b1, g1, be1);
    k_conv<<<1184, 256>>>(h1, h2, W2, b2, g2, be2);

    k_poolcls<<<NG, 64>>>(gid, Wc1, bc1, g3, be3, Wc2, bc2, g4, be4, Wc3, bc3, out);
}

// round 3
// speedup vs baseline: 1.3706x; 1.3706x over previous
#include <cuda_runtime.h>
#include <math.h>

#define NN 100000
#define NE 1200000
#define D  64
#define NG 512

// -------- scratch (device globals; no allocation) --------
static __device__ float g_h1 [NN * D];   // conv1 output
static __device__ float g_h2 [NN * D];   // conv2 output
static __device__ float g_ns [NN];
static __device__ float g_nd [NN];
static __device__ int   g_dego[NN];
static __device__ int   g_degi[NN];
static __device__ int   g_off [NN];      // bucket base per dst node (unordered CSR)
static __device__ int   g_cur [NN];      // fill cursors
static __device__ int   g_csrc[NE];      // src node per bucketed edge
static __device__ int   g_total;         // bucket allocator counter

// -------- init --------
__global__ void k_zero() {
    int i = blockIdx.x * blockDim.x + threadIdx.x;
    if (i < NN) { g_dego[i] = 0; g_degi[i] = 0; }
    if (i == 0) g_total = 0;
}

// -------- degrees --------
__global__ void k_deg(const int* __restrict__ src, const int* __restrict__ dst) {
    int e = blockIdx.x * blockDim.x + threadIdx.x;
    if (e < NE) {
        atomicAdd(&g_dego[src[e]], 1);
        atomicAdd(&g_degi[dst[e]], 1);
    }
}

// -------- norms + parallel bucket allocation (no ordered scan needed) --------
__global__ void k_norm() {
    int i = blockIdx.x * blockDim.x + threadIdx.x;
    if (i < NN) {
        int dov = g_dego[i]; if (dov < 1) dov = 1;
        int div_ = g_degi[i]; if (div_ < 1) div_ = 1;
        g_ns[i] = rsqrtf((float)dov);
        g_nd[i] = rsqrtf((float)div_);
        // warp-aggregated allocation of bucket space
        int deg = g_degi[i];
        int base = atomicAdd(&g_total, deg);
        g_off[i] = base;
        g_cur[i] = base;
    }
}

// -------- bucket edges by dst --------
__global__ void k_fill(const int* __restrict__ src, const int* __restrict__ dst) {
    int e = blockIdx.x * blockDim.x + threadIdx.x;
    if (e < NE) {
        int d = dst[e];
        int p = atomicAdd(&g_cur[d], 1);
        g_csrc[p] = src[e];
    }
}

// -------- fused conv: gather-sum + (·nd) @ W + b, LN, ReLU --------
__global__ void k_conv(const float* __restrict__ x, float* __restrict__ y,
                       const float* __restrict__ W, const float* __restrict__ b,
                       const float* __restrict__ gm, const float* __restrict__ bt) {
    __shared__ float Ws[64 * 64];
    int tid = threadIdx.x;
    for (int i = tid; i < 64 * 64; i += blockDim.x) Ws[i] = W[i];
    __syncthreads();

    int lane  = tid & 31;
    int wid   = tid >> 5;
    int nwarp = (gridDim.x * blockDim.x) >> 5;

    for (int n = blockIdx.x * (blockDim.x >> 5) + wid; n < NN; n += nwarp) {
        int off = __ldg(&g_off[n]);
        int end = off + __ldg(&g_degi[n]);
        float acc0 = 0.f, acc1 = 0.f;
        #pragma unroll 4
        for (int e = off; e < end; e++) {
            int s = __ldg(&g_csrc[e]);
            float nsv = __ldg(&g_ns[s]);
            acc0 += __ldg(&x[s * 64 + lane])      * nsv;
            acc1 += __ldg(&x[s * 64 + 32 + lane]) * nsv;
        }
        float ndv = g_nd[n];
        float a0 = acc0 * ndv;
        float a1 = acc1 * ndv;

        float r0 = b[lane];
        float r1 = b[lane + 32];
        #pragma unroll
        for (int k = 0; k < 32; k++) {
            float xk = __shfl_sync(0xffffffffu, a0, k);
            r0 += xk * Ws[k * 64 + lane];
            r1 += xk * Ws[k * 64 + 32 + lane];
        }
        #pragma unroll
        for (int k = 0; k < 32; k++) {
            float xk = __shfl_sync(0xffffffffu, a1, k);
            r0 += xk * Ws[(k + 32) * 64 + lane];
            r1 += xk * Ws[(k + 32) * 64 + 32 + lane];
        }
        // LayerNorm over 64 (2 vals/lane) + ReLU
        float s = r0 + r1;
        #pragma unroll
        for (int o = 16; o; o >>= 1) s += __shfl_xor_sync(0xffffffffu, s, o);
        float mean = s * (1.f / 64.f);
        float d0 = r0 - mean, d1 = r1 - mean;
        float vv = d0 * d0 + d1 * d1;
        #pragma unroll
        for (int o = 16; o; o >>= 1) vv += __shfl_xor_sync(0xffffffffu, vv, o);
        float inv = rsqrtf(vv * (1.f / 64.f) + 1e-5f);
        float y0 = d0 * inv * gm[lane]      + bt[lane];
        float y1 = d1 * inv * gm[lane + 32] + bt[lane + 32];
        y[n * 64 + lane]      = fmaxf(y0, 0.f);
        y[n * 64 + 32 + lane] = fmaxf(y1, 0.f);
    }
}

// -------- fused pool (sorted graph_ids, binary search) + classifier head --------
__global__ void k_poolcls(const int* __restrict__ gid,
                          const float* __restrict__ Wc1, const float* __restrict__ bc1,
                          const float* __restrict__ g3,  const float* __restrict__ be3,
                          const float* __restrict__ Wc2, const float* __restrict__ bc2,
                          const float* __restrict__ g4,  const float* __restrict__ be4,
                          const float* __restrict__ Wc3, const float* __restrict__ bc3,
                          float* __restrict__ out) {
    __shared__ float hA[64], hB[64], o1[64], red[64];
    int g = blockIdx.x, t = threadIdx.x;

    // binary search node range for graph g (gid sorted)
    int lo = 0, hi = NN;
    while (lo < hi) { int mid = (lo + hi) >> 1; if (__ldg(&gid[mid]) < g)     lo = mid + 1; else hi = mid; }
    int start = lo;
    lo = start; hi = NN;
    while (lo < hi) { int mid = (lo + hi) >> 1; if (__ldg(&gid[mid]) < g + 1) lo = mid + 1; else hi = mid; }
    int end = lo;

    float s = 0.f, m = 0.f;   // post-ReLU values >= 0, so max init 0 is safe
    for (int n = start; n < end; n++) {
        float v = g_h2[n * 64 + t];
        s += v;
        m = fmaxf(m, v);
    }
    float cnt = (float)(end - start); if (cnt < 1.f) cnt = 1.f;
    float mv = s / cnt;
    float xv = m;

    // l2 norm of mean vec
    red[t] = mv * mv; __syncthreads();
    for (int o = 32; o; o >>= 1) { if (t < o) red[t] += red[t + o]; __syncthreads(); }
    float nA = fmaxf(sqrtf(red[0]), 1e-12f); __syncthreads();
    // l2 norm of max vec
    red[t] = xv * xv; __syncthreads();
    for (int o = 32; o; o >>= 1) { if (t < o) red[t] += red[t + o]; __syncthreads(); }
    float nB = fmaxf(sqrtf(red[0]), 1e-12f); __syncthreads();

    hA[t] = mv / nA;
    hB[t] = xv / nB;
    __syncthreads();

    // layer 1: [128] @ Wc1[128,64]
    float acc = bc1[t];
    #pragma unroll 4
    for (int k = 0; k < 64; k++) acc += hA[k] * Wc1[k * 64 + t];
    #pragma unroll 4
    for (int k = 0; k < 64; k++) acc += hB[k] * Wc1[(64 + k) * 64 + t];
    red[t] = acc; __syncthreads();
    for (int o = 32; o; o >>= 1) { if (t < o) red[t] += red[t + o]; __syncthreads(); }
    float mean = red[0] * (1.f / 64.f); __syncthreads();
    float dv = acc - mean;
    red[t] = dv * dv; __syncthreads();
    for (int o = 32; o; o >>= 1) { if (t < o) red[t] += red[t + o]; __syncthreads(); }
    float inv = rsqrtf(red[0] * (1.f / 64.f) + 1e-5f); __syncthreads();
    o1[t] = fmaxf(dv * inv * g3[t] + be3[t], 0.f);
    __syncthreads();

    // layer 2: [64] @ Wc2[64,64]
    acc = bc2[t];
    #pragma unroll 4
    for (int k = 0; k < 64; k++) acc += o1[k] * Wc2[k * 64 + t];
    red[t] = acc; __syncthreads();
    for (int o = 32; o; o >>= 1) { if (t < o) red[t] += red[t + o]; __syncthreads(); }
    mean = red[0] * (1.f / 64.f); __syncthreads();
    dv = acc - mean;
    red[t] = dv * dv; __syncthreads();
    for (int o = 32; o; o >>= 1) { if (t < o) red[t] += red[t + o]; __syncthreads(); }
    inv = rsqrtf(red[0] * (1.f / 64.f) + 1e-5f); __syncthreads();
    float o2 = fmaxf(dv * inv * g4[t] + be4[t], 0.f);

    // layer 3: [64] @ Wc3[64,1]
    red[t] = o2 * Wc3[t]; __syncthreads();
    for (int o = 32; o; o >>= 1) { if (t < o) red[t] += red[t + o]; __syncthreads(); }
    if (t == 0) out[g] = red[0] + bc3[0];
}

extern "C" void kernel_launch(void* const* d_in, const int* in_sizes, int n_in,
                              void* d_out, int out_size) {
    const float* h   = (const float*)d_in[0];
    const int*   src = (const int*)  d_in[1];
    const int*   dst = (const int*)  d_in[2];
    const int*   gid = (const int*)  d_in[3];
    const float* W1  = (const float*)d_in[4];
    const float* b1  = (const float*)d_in[5];
    const float* W2  = (const float*)d_in[6];
    const float* b2  = (const float*)d_in[7];
    const float* g1  = (const float*)d_in[8];
    const float* be1 = (const float*)d_in[9];
    const float* g2  = (const float*)d_in[10];
    const float* be2 = (const float*)d_in[11];
    const float* g3  = (const float*)d_in[12];
    const float* be3 = (const float*)d_in[13];
    const float* g4  = (const float*)d_in[14];
    const float* be4 = (const float*)d_in[15];
    const float* Wc1 = (const float*)d_in[16];
    const float* bc1 = (const float*)d_in[17];
    const float* Wc2 = (const float*)d_in[18];
    const float* bc2 = (const float*)d_in[19];
    const float* Wc3 = (const float*)d_in[20];
    const float* bc3 = (const float*)d_in[21];
    float* out = (float*)d_out;

    float* h1 = nullptr; float* h2 = nullptr;
    cudaGetSymbolAddress((void**)&h1, g_h1);
    cudaGetSymbolAddress((void**)&h2, g_h2);

    k_zero<<<(NN + 255) / 256, 256>>>();
    k_deg <<<(NE + 255) / 256, 256>>>(src, dst);
    k_norm<<<(NN + 255) / 256, 256>>>();
    k_fill<<<(NE + 255) / 256, 256>>>(src, dst);

    k_conv<<<1184, 256>>>(h,  h1, W1, b1, g1, be1);
    k_conv<<<1184, 256>>>(h1, h2, W2, b2, g2, be2);

    k_poolcls<<<NG, 64>>>(gid, Wc1, bc1, g3, be3, Wc2, bc2, g4, be4, Wc3, bc3, out);
}

// round 4
// speedup vs baseline: 2.2179x; 1.6182x over previous
#include <cuda_runtime.h>
#include <math.h>

#define NN 100000
#define NE 1200000
#define D  64
#define NG 512

// -------- scratch (device globals; no allocation) --------
static __device__ float g_agg[NN * D];   // aggregated features
static __device__ float g_h1 [NN * D];   // conv1 output
static __device__ float g_h2 [NN * D];   // conv2 output
static __device__ float g_ns [NN];
static __device__ float g_nd [NN];
static __device__ int   g_dego[NN];
static __device__ int   g_degi[NN];
static __device__ int   g_off [NN];      // bucket base per dst node (unordered CSR)
static __device__ int   g_cur [NN];      // fill cursors
static __device__ int   g_csrc[NE];      // src node per bucketed edge
static __device__ int   g_total;         // bucket allocator counter

// -------- init --------
__global__ void k_zero() {
    int i = blockIdx.x * blockDim.x + threadIdx.x;
    if (i < NN) { g_dego[i] = 0; g_degi[i] = 0; }
    if (i == 0) g_total = 0;
}

// -------- degrees --------
__global__ void k_deg(const int* __restrict__ src, const int* __restrict__ dst) {
    int e = blockIdx.x * blockDim.x + threadIdx.x;
    if (e < NE) {
        atomicAdd(&g_dego[src[e]], 1);
        atomicAdd(&g_degi[dst[e]], 1);
    }
}

// -------- norms + parallel bucket allocation --------
__global__ void k_norm() {
    int i = blockIdx.x * blockDim.x + threadIdx.x;
    if (i < NN) {
        int dov = g_dego[i]; if (dov < 1) dov = 1;
        int div_ = g_degi[i]; if (div_ < 1) div_ = 1;
        g_ns[i] = rsqrtf((float)dov);
        g_nd[i] = rsqrtf((float)div_);
        int deg = g_degi[i];
        int base = atomicAdd(&g_total, deg);
        g_off[i] = base;
        g_cur[i] = base;
    }
}

// -------- bucket edges by dst --------
__global__ void k_fill(const int* __restrict__ src, const int* __restrict__ dst) {
    int e = blockIdx.x * blockDim.x + threadIdx.x;
    if (e < NE) {
        int d = dst[e];
        int p = atomicAdd(&g_cur[d], 1);
        g_csrc[p] = src[e];
    }
}

// -------- gather: agg[n] = nd[n] * sum_{e: dst=n} ns[src] * x[src] --------
// One warp per node; lanes 0-15 handle even edges, 16-31 odd edges.
// Each lane accumulates a float4 slice (16 lanes x 4 floats = 64 feats).
__global__ void k_gather(const float* __restrict__ x) {
    int gw = (blockIdx.x * blockDim.x + threadIdx.x) >> 5;
    if (gw >= NN) return;
    int lane = threadIdx.x & 31;
    int half = lane >> 4;
    int li   = lane & 15;

    int off = __ldg(&g_off[gw]);
    int deg = __ldg(&g_degi[gw]);
    const float4* x4 = (const float4*)x;

    float4 acc = make_float4(0.f, 0.f, 0.f, 0.f);
    for (int e = off + half; e < off + deg; e += 2) {
        int s = __ldg(&g_csrc[e]);
        float nsv = __ldg(&g_ns[s]);
        float4 v = __ldg(&x4[s * 16 + li]);
        acc.x += v.x * nsv; acc.y += v.y * nsv;
        acc.z += v.z * nsv; acc.w += v.w * nsv;
    }
    acc.x += __shfl_xor_sync(0xffffffffu, acc.x, 16);
    acc.y += __shfl_xor_sync(0xffffffffu, acc.y, 16);
    acc.z += __shfl_xor_sync(0xffffffffu, acc.z, 16);
    acc.w += __shfl_xor_sync(0xffffffffu, acc.w, 16);

    if (half == 0) {
        float ndv = g_nd[gw];
        ((float4*)g_agg)[gw * 16 + li] =
            make_float4(acc.x * ndv, acc.y * ndv, acc.z * ndv, acc.w * ndv);
    }
}

// -------- tiled GEMM [NN,64] @ W[64,64] + b, LN, ReLU --------
// Block: 256 threads; tile: 64 rows x 64 cols; thread computes 4x4.
__global__ void __launch_bounds__(256) k_gemm_ln(
        float* __restrict__ y,
        const float* __restrict__ W, const float* __restrict__ b,
        const float* __restrict__ gm, const float* __restrict__ bt) {
    __shared__ float Xs[64 * 64];
    __shared__ float Ws[64 * 64];

    int tid = threadIdx.x;
    int base = blockIdx.x * 64;   // first row of this tile

    // load X tile (guard rows) and W, as float4
    const float4* agg4 = (const float4*)g_agg;
    const float4* W4 = (const float4*)W;
    #pragma unroll
    for (int i = 0; i < 4; i++) {
        int idx = tid + i * 256;            // over 1024 float4s
        int row = base + (idx >> 4);
        ((float4*)Xs)[idx] = (row < NN) ? __ldg(&agg4[row * 16 + (idx & 15)])
                                        : make_float4(0.f, 0.f, 0.f, 0.f);
        ((float4*)Ws)[idx] = __ldg(&W4[idx]);
    }
    __syncthreads();

    int R = tid >> 4;   // row group 0..15 (rows R*4..R*4+3)
    int C = tid & 15;   // col group 0..15 (cols C*4..C*4+3)

    float acc[4][4];
    #pragma unroll
    for (int r = 0; r < 4; r++)
        #pragma unroll
        for (int c = 0; c < 4; c++) acc[r][c] = 0.f;

    #pragma unroll 4
    for (int k = 0; k < 64; k++) {
        float4 bv = ((const float4*)Ws)[k * 16 + C];
        float a0 = Xs[(R * 4 + 0) * 64 + k];
        float a1 = Xs[(R * 4 + 1) * 64 + k];
        float a2 = Xs[(R * 4 + 2) * 64 + k];
        float a3 = Xs[(R * 4 + 3) * 64 + k];
        acc[0][0] += a0 * bv.x; acc[0][1] += a0 * bv.y; acc[0][2] += a0 * bv.z; acc[0][3] += a0 * bv.w;
        acc[1][0] += a1 * bv.x; acc[1][1] += a1 * bv.y; acc[1][2] += a1 * bv.z; acc[1][3] += a1 * bv.w;
        acc[2][0] += a2 * bv.x; acc[2][1] += a2 * bv.y; acc[2][2] += a2 * bv.z; acc[2][3] += a2 * bv.w;
        acc[3][0] += a3 * bv.x; acc[3][1] += a3 * bv.y; acc[3][2] += a3 * bv.z; acc[3][3] += a3 * bv.w;
    }

    float4 bias = ((const float4*)b)[C];
    float4 gmv  = ((const float4*)gm)[C];
    float4 btv  = ((const float4*)bt)[C];

    #pragma unroll
    for (int r = 0; r < 4; r++) {
        float o0 = acc[r][0] + bias.x;
        float o1 = acc[r][1] + bias.y;
        float o2 = acc[r][2] + bias.z;
        float o3 = acc[r][3] + bias.w;
        // row mean over 64 (16 lanes x 4): shfl within 16-lane group
        float s = o0 + o1 + o2 + o3;
        #pragma unroll
        for (int m = 1; m < 16; m <<= 1) s += __shfl_xor_sync(0xffffffffu, s, m);
        float mean = s * (1.f / 64.f);
        float d0 = o0 - mean, d1 = o1 - mean, d2 = o2 - mean, d3 = o3 - mean;
        float vv = d0 * d0 + d1 * d1 + d2 * d2 + d3 * d3;
        #pragma unroll
        for (int m = 1; m < 16; m <<= 1) vv += __shfl_xor_sync(0xffffffffu, vv, m);
        float inv = rsqrtf(vv * (1.f / 64.f) + 1e-5f);
        float4 outv;
        outv.x = fmaxf(d0 * inv * gmv.x + btv.x, 0.f);
        outv.y = fmaxf(d1 * inv * gmv.y + btv.y, 0.f);
        outv.z = fmaxf(d2 * inv * gmv.z + btv.z, 0.f);
        outv.w = fmaxf(d3 * inv * gmv.w + btv.w, 0.f);
        int row = base + R * 4 + r;
        if (row < NN) ((float4*)y)[row * 16 + C] = outv;
    }
}

// -------- fused pool (sorted graph_ids, binary search) + classifier head --------
__global__ void k_poolcls(const int* __restrict__ gid,
                          const float* __restrict__ Wc1, const float* __restrict__ bc1,
                          const float* __restrict__ g3,  const float* __restrict__ be3,
                          const float* __restrict__ Wc2, const float* __restrict__ bc2,
                          const float* __restrict__ g4,  const float* __restrict__ be4,
                          const float* __restrict__ Wc3, const float* __restrict__ bc3,
                          float* __restrict__ out) {
    __shared__ float hA[64], hB[64], o1[64], red[64];
    int g = blockIdx.x, t = threadIdx.x;

    int lo = 0, hi = NN;
    while (lo < hi) { int mid = (lo + hi) >> 1; if (__ldg(&gid[mid]) < g)     lo = mid + 1; else hi = mid; }
    int start = lo;
    lo = start; hi = NN;
    while (lo < hi) { int mid = (lo + hi) >> 1; if (__ldg(&gid[mid]) < g + 1) lo = mid + 1; else hi = mid; }
    int end = lo;

    float s = 0.f, m = 0.f;   // post-ReLU values >= 0
    for (int n = start; n < end; n++) {
        float v = g_h2[n * 64 + t];
        s += v;
        m = fmaxf(m, v);
    }
    float cnt = (float)(end - start); if (cnt < 1.f) cnt = 1.f;
    float mv = s / cnt;
    float xv = m;

    red[t] = mv * mv; __syncthreads();
    for (int o = 32; o; o >>= 1) { if (t < o) red[t] += red[t + o]; __syncthreads(); }
    float nA = fmaxf(sqrtf(red[0]), 1e-12f); __syncthreads();
    red[t] = xv * xv; __syncthreads();
    for (int o = 32; o; o >>= 1) { if (t < o) red[t] += red[t + o]; __syncthreads(); }
    float nB = fmaxf(sqrtf(red[0]), 1e-12f); __syncthreads();

    hA[t] = mv / nA;
    hB[t] = xv / nB;
    __syncthreads();

    float acc = bc1[t];
    #pragma unroll 4
    for (int k = 0; k < 64; k++) acc += hA[k] * Wc1[k * 64 + t];
    #pragma unroll 4
    for (int k = 0; k < 64; k++) acc += hB[k] * Wc1[(64 + k) * 64 + t];
    red[t] = acc; __syncthreads();
    for (int o = 32; o; o >>= 1) { if (t < o) red[t] += red[t + o]; __syncthreads(); }
    float mean = red[0] * (1.f / 64.f); __syncthreads();
    float dv = acc - mean;
    red[t] = dv * dv; __syncthreads();
    for (int o = 32; o; o >>= 1) { if (t < o) red[t] += red[t + o]; __syncthreads(); }
    float inv = rsqrtf(red[0] * (1.f / 64.f) + 1e-5f); __syncthreads();
    o1[t] = fmaxf(dv * inv * g3[t] + be3[t], 0.f);
    __syncthreads();

    acc = bc2[t];
    #pragma unroll 4
    for (int k = 0; k < 64; k++) acc += o1[k] * Wc2[k * 64 + t];
    red[t] = acc; __syncthreads();
    for (int o = 32; o; o >>= 1) { if (t < o) red[t] += red[t + o]; __syncthreads(); }
    mean = red[0] * (1.f / 64.f); __syncthreads();
    dv = acc - mean;
    red[t] = dv * dv; __syncthreads();
    for (int o = 32; o; o >>= 1) { if (t < o) red[t] += red[t + o]; __syncthreads(); }
    inv = rsqrtf(red[0] * (1.f / 64.f) + 1e-5f); __syncthreads();
    float o2 = fmaxf(dv * inv * g4[t] + be4[t], 0.f);

    red[t] = o2 * Wc3[t]; __syncthreads();
    for (int o = 32; o; o >>= 1) { if (t < o) red[t] += red[t + o]; __syncthreads(); }
    if (t == 0) out[g] = red[0] + bc3[0];
}

extern "C" void kernel_launch(void* const* d_in, const int* in_sizes, int n_in,
                              void* d_out, int out_size) {
    const float* h   = (const float*)d_in[0];
    const int*   src = (const int*)  d_in[1];
    const int*   dst = (const int*)  d_in[2];
    const int*   gid = (const int*)  d_in[3];
    const float* W1  = (const float*)d_in[4];
    const float* b1  = (const float*)d_in[5];
    const float* W2  = (const float*)d_in[6];
    const float* b2  = (const float*)d_in[7];
    const float* g1  = (const float*)d_in[8];
    const float* be1 = (const float*)d_in[9];
    const float* g2  = (const float*)d_in[10];
    const float* be2 = (const float*)d_in[11];
    const float* g3  = (const float*)d_in[12];
    const float* be3 = (const float*)d_in[13];
    const float* g4  = (const float*)d_in[14];
    const float* be4 = (const float*)d_in[15];
    const float* Wc1 = (const float*)d_in[16];
    const float* bc1 = (const float*)d_in[17];
    const float* Wc2 = (const float*)d_in[18];
    const float* bc2 = (const float*)d_in[19];
    const float* Wc3 = (const float*)d_in[20];
    const float* bc3 = (const float*)d_in[21];
    float* out = (float*)d_out;

    float* h1 = nullptr; float* h2 = nullptr;
    cudaGetSymbolAddress((void**)&h1, g_h1);
    cudaGetSymbolAddress((void**)&h2, g_h2);

    k_zero<<<(NN + 255) / 256, 256>>>();
    k_deg <<<(NE + 255) / 256, 256>>>(src, dst);
    k_norm<<<(NN + 255) / 256, 256>>>();
    k_fill<<<(NE + 255) / 256, 256>>>(src, dst);

    // conv 1
    k_gather <<<(NN * 32 + 255) / 256, 256>>>(h);
    k_gemm_ln<<<(NN + 63) / 64, 256>>>(h1, W1, b1, g1, be1);
    // conv 2
    k_gather <<<(NN * 32 + 255) / 256, 256>>>(h1);
    k_gemm_ln<<<(NN + 63) / 64, 256>>>(h2, W2, b2, g2, be2);

    k_poolcls<<<NG, 64>>>(gid, Wc1, bc1, g3, be3, Wc2, bc2, g4, be4, Wc3, bc3, out);
}

// round 5
// speedup vs baseline: 2.2220x; 1.0019x over previous
#include <cuda_runtime.h>
#include <cuda_fp16.h>
#include <math.h>

#define NN 100000
#define NE 1200000
#define NG 512

// -------- scratch (device globals; no allocation) --------
static __device__ __half2 g_xh [NN * 32];  // fp16 x*ns (conv1 input)
static __device__ __half2 g_h1h[NN * 32];  // fp16 h1*ns (conv2 input)
static __device__ float   g_h2 [NN * 64];  // conv2 output (fp32, for pooling)
static __device__ float   g_ns [NN];
static __device__ float   g_nd [NN];
static __device__ int     g_dego[NN];
static __device__ int     g_degi[NN];
static __device__ int     g_off [NN];
static __device__ int     g_cur [NN];
static __device__ int     g_csrc[NE];
static __device__ int     g_total;
static __device__ float   g_pool[NG * 128]; // [mean(64) | max(64)] per graph

// -------- init --------
__global__ void k_zero() {
    int i = blockIdx.x * blockDim.x + threadIdx.x;
    if (i < NN) { g_dego[i] = 0; g_degi[i] = 0; }
    if (i == 0) g_total = 0;
}

// -------- degrees (4 edges/thread) --------
__global__ void k_deg(const int4* __restrict__ src4, const int4* __restrict__ dst4) {
    int i = blockIdx.x * blockDim.x + threadIdx.x;
    if (i < NE / 4) {
        int4 s = __ldg(&src4[i]);
        int4 d = __ldg(&dst4[i]);
        atomicAdd(&g_dego[s.x], 1); atomicAdd(&g_dego[s.y], 1);
        atomicAdd(&g_dego[s.z], 1); atomicAdd(&g_dego[s.w], 1);
        atomicAdd(&g_degi[d.x], 1); atomicAdd(&g_degi[d.y], 1);
        atomicAdd(&g_degi[d.z], 1); atomicAdd(&g_degi[d.w], 1);
    }
}

// -------- norms + parallel bucket allocation --------
__global__ void k_norm() {
    int i = blockIdx.x * blockDim.x + threadIdx.x;
    if (i < NN) {
        int dov = g_dego[i]; if (dov < 1) dov = 1;
        int div_ = g_degi[i]; if (div_ < 1) div_ = 1;
        g_ns[i] = rsqrtf((float)dov);
        g_nd[i] = rsqrtf((float)div_);
        int deg = g_degi[i];
        int base = atomicAdd(&g_total, deg);
        g_off[i] = base;
        g_cur[i] = base;
    }
}

// -------- bucket edges by dst (4 edges/thread) --------
__global__ void k_fill(const int4* __restrict__ src4, const int4* __restrict__ dst4) {
    int i = blockIdx.x * blockDim.x + threadIdx.x;
    if (i < NE / 4) {
        int4 s = __ldg(&src4[i]);
        int4 d = __ldg(&dst4[i]);
        g_csrc[atomicAdd(&g_cur[d.x], 1)] = s.x;
        g_csrc[atomicAdd(&g_cur[d.y], 1)] = s.y;
        g_csrc[atomicAdd(&g_cur[d.z], 1)] = s.z;
        g_csrc[atomicAdd(&g_cur[d.w], 1)] = s.w;
    }
}

// -------- prep: g_xh = half(x * ns) --------
__global__ void k_prep(const float* __restrict__ x) {
    int i = blockIdx.x * blockDim.x + threadIdx.x;   // over NN*16 float4s
    if (i < NN * 16) {
        float4 v = __ldg(&((const float4*)x)[i]);
        float s = g_ns[i >> 4];
        g_xh[i * 2]     = __floats2half2_rn(v.x * s, v.y * s);
        g_xh[i * 2 + 1] = __floats2half2_rn(v.z * s, v.w * s);
    }
}

// -------- fused conv: gather (fp16) -> smem tile -> GEMM -> LN/ReLU -> out --------
// Block 256 threads = 8 warps; 64 nodes/block (8 per warp).
// last=0: writes half(y*ns) to g_h1h ; last=1: writes fp32 y to g_h2.
__global__ void __launch_bounds__(256) k_conv(
        const __half2* __restrict__ xin, int last,
        const float* __restrict__ W, const float* __restrict__ b,
        const float* __restrict__ gm, const float* __restrict__ bt) {
    __shared__ float Xs[64 * 64];
    __shared__ float Ws[64 * 64];

    int tid  = threadIdx.x;
    int base = blockIdx.x * 64;
    int wid  = tid >> 5;
    int lane = tid & 31;
    int half = lane >> 4;
    int li   = lane & 15;

    // load W (no sync needed until after gather)
    const float4* W4 = (const float4*)W;
    #pragma unroll
    for (int i = 0; i < 4; i++)
        ((float4*)Ws)[tid + i * 256] = __ldg(&W4[tid + i * 256]);

    // gather 8 nodes per warp
    #pragma unroll 1
    for (int j = 0; j < 8; j++) {
        int n = base + wid * 8 + j;
        float4 acc = make_float4(0.f, 0.f, 0.f, 0.f);
        if (n < NN) {
            int off = __ldg(&g_off[n]);
            int deg = __ldg(&g_degi[n]);
            const uint2* xin2 = (const uint2*)xin;
            for (int e = off + half; e < off + deg; e += 2) {
                int s = __ldg(&g_csrc[e]);
                uint2 u = __ldg(&xin2[s * 16 + li]);
                __half2 h0 = *reinterpret_cast<__half2*>(&u.x);
                __half2 h1 = *reinterpret_cast<__half2*>(&u.y);
                float2 f0 = __half22float2(h0);
                float2 f1 = __half22float2(h1);
                acc.x += f0.x; acc.y += f0.y;
                acc.z += f1.x; acc.w += f1.y;
            }
        }
        acc.x += __shfl_xor_sync(0xffffffffu, acc.x, 16);
        acc.y += __shfl_xor_sync(0xffffffffu, acc.y, 16);
        acc.z += __shfl_xor_sync(0xffffffffu, acc.z, 16);
        acc.w += __shfl_xor_sync(0xffffffffu, acc.w, 16);
        if (half == 0) {
            float ndv = (n < NN) ? g_nd[n] : 0.f;
            ((float4*)Xs)[(wid * 8 + j) * 16 + li] =
                make_float4(acc.x * ndv, acc.y * ndv, acc.z * ndv, acc.w * ndv);
        }
    }
    __syncthreads();

    // GEMM: thread computes 4x4
    int R = tid >> 4;
    int C = tid & 15;
    float acc[4][4];
    #pragma unroll
    for (int r = 0; r < 4; r++)
        #pragma unroll
        for (int c = 0; c < 4; c++) acc[r][c] = 0.f;

    #pragma unroll 4
    for (int k = 0; k < 64; k++) {
        float4 bv = ((const float4*)Ws)[k * 16 + C];
        float a0 = Xs[(R * 4 + 0) * 64 + k];
        float a1 = Xs[(R * 4 + 1) * 64 + k];
        float a2 = Xs[(R * 4 + 2) * 64 + k];
        float a3 = Xs[(R * 4 + 3) * 64 + k];
        acc[0][0] += a0 * bv.x; acc[0][1] += a0 * bv.y; acc[0][2] += a0 * bv.z; acc[0][3] += a0 * bv.w;
        acc[1][0] += a1 * bv.x; acc[1][1] += a1 * bv.y; acc[1][2] += a1 * bv.z; acc[1][3] += a1 * bv.w;
        acc[2][0] += a2 * bv.x; acc[2][1] += a2 * bv.y; acc[2][2] += a2 * bv.z; acc[2][3] += a2 * bv.w;
        acc[3][0] += a3 * bv.x; acc[3][1] += a3 * bv.y; acc[3][2] += a3 * bv.z; acc[3][3] += a3 * bv.w;
    }

    float4 bias = ((const float4*)b)[C];
    float4 gmv  = ((const float4*)gm)[C];
    float4 btv  = ((const float4*)bt)[C];

    #pragma unroll
    for (int r = 0; r < 4; r++) {
        int row = base + R * 4 + r;
        float o0 = acc[r][0] + bias.x;
        float o1 = acc[r][1] + bias.y;
        float o2 = acc[r][2] + bias.z;
        float o3 = acc[r][3] + bias.w;
        float s = o0 + o1 + o2 + o3;
        #pragma unroll
        for (int m = 1; m < 16; m <<= 1) s += __shfl_xor_sync(0xffffffffu, s, m);
        float mean = s * (1.f / 64.f);
        float d0 = o0 - mean, d1 = o1 - mean, d2 = o2 - mean, d3 = o3 - mean;
        float vv = d0 * d0 + d1 * d1 + d2 * d2 + d3 * d3;
        #pragma unroll
        for (int m = 1; m < 16; m <<= 1) vv += __shfl_xor_sync(0xffffffffu, vv, m);
        float inv = rsqrtf(vv * (1.f / 64.f) + 1e-5f);
        float y0 = fmaxf(d0 * inv * gmv.x + btv.x, 0.f);
        float y1 = fmaxf(d1 * inv * gmv.y + btv.y, 0.f);
        float y2 = fmaxf(d2 * inv * gmv.z + btv.z, 0.f);
        float y3 = fmaxf(d3 * inv * gmv.w + btv.w, 0.f);
        if (row < NN) {
            if (last) {
                ((float4*)g_h2)[row * 16 + C] = make_float4(y0, y1, y2, y3);
            } else {
                float nsr = g_ns[row];
                g_h1h[row * 32 + C * 2]     = __floats2half2_rn(y0 * nsr, y1 * nsr);
                g_h1h[row * 32 + C * 2 + 1] = __floats2half2_rn(y2 * nsr, y3 * nsr);
            }
        }
    }
}

// -------- pooling: block per graph, 256 threads (4 row-chunks x 64 cols) --------
__global__ void k_pool(const int* __restrict__ gid) {
    __shared__ float ss[256], mm[256];
    int g = blockIdx.x;
    int t = threadIdx.x;
    int col = t & 63;
    int chunk = t >> 6;

    int lo = 0, hi = NN;
    while (lo < hi) { int mid = (lo + hi) >> 1; if (__ldg(&gid[mid]) < g)     lo = mid + 1; else hi = mid; }
    int start = lo;
    lo = start; hi = NN;
    while (lo < hi) { int mid = (lo + hi) >> 1; if (__ldg(&gid[mid]) < g + 1) lo = mid + 1; else hi = mid; }
    int end = lo;

    float s = 0.f, m = 0.f;   // post-ReLU >= 0
    for (int n = start + chunk; n < end; n += 4) {
        float v = g_h2[n * 64 + col];
        s += v;
        m = fmaxf(m, v);
    }
    ss[t] = s; mm[t] = m;
    __syncthreads();
    if (chunk == 0) {
        s = ss[col] + ss[64 + col] + ss[128 + col] + ss[192 + col];
        m = fmaxf(fmaxf(mm[col], mm[64 + col]), fmaxf(mm[128 + col], mm[192 + col]));
        float cnt = (float)(end - start); if (cnt < 1.f) cnt = 1.f;
        g_pool[g * 128 + col]      = s / cnt;
        g_pool[g * 128 + 64 + col] = m;
    }
}

// -------- classifier head: block (64 threads) per graph --------
__global__ void k_cls(const float* __restrict__ Wc1, const float* __restrict__ bc1,
                      const float* __restrict__ g3,  const float* __restrict__ be3,
                      const float* __restrict__ Wc2, const float* __restrict__ bc2,
                      const float* __restrict__ g4,  const float* __restrict__ be4,
                      const float* __restrict__ Wc3, const float* __restrict__ bc3,
                      float* __restrict__ out) {
    __shared__ float hA[64], hB[64], o1[64], red[64];
    int g = blockIdx.x, t = threadIdx.x;

    float mv = g_pool[g * 128 + t];
    float xv = g_pool[g * 128 + 64 + t];

    red[t] = mv * mv; __syncthreads();
    for (int o = 32; o; o >>= 1) { if (t < o) red[t] += red[t + o]; __syncthreads(); }
    float nA = fmaxf(sqrtf(red[0]), 1e-12f); __syncthreads();
    red[t] = xv * xv; __syncthreads();
    for (int o = 32; o; o >>= 1) { if (t < o) red[t] += red[t + o]; __syncthreads(); }
    float nB = fmaxf(sqrtf(red[0]), 1e-12f); __syncthreads();

    hA[t] = mv / nA;
    hB[t] = xv / nB;
    __syncthreads();

    float acc = bc1[t];
    #pragma unroll 4
    for (int k = 0; k < 64; k++) acc += hA[k] * Wc1[k * 64 + t];
    #pragma unroll 4
    for (int k = 0; k < 64; k++) acc += hB[k] * Wc1[(64 + k) * 64 + t];
    red[t] = acc; __syncthreads();
    for (int o = 32; o; o >>= 1) { if (t < o) red[t] += red[t + o]; __syncthreads(); }
    float mean = red[0] * (1.f / 64.f); __syncthreads();
    float dv = acc - mean;
    red[t] = dv * dv; __syncthreads();
    for (int o = 32; o; o >>= 1) { if (t < o) red[t] += red[t + o]; __syncthreads(); }
    float inv = rsqrtf(red[0] * (1.f / 64.f) + 1e-5f); __syncthreads();
    o1[t] = fmaxf(dv * inv * g3[t] + be3[t], 0.f);
    __syncthreads();

    acc = bc2[t];
    #pragma unroll 4
    for (int k = 0; k < 64; k++) acc += o1[k] * Wc2[k * 64 + t];
    red[t] = acc; __syncthreads();
    for (int o = 32; o; o >>= 1) { if (t < o) red[t] += red[t + o]; __syncthreads(); }
    mean = red[0] * (1.f / 64.f); __syncthreads();
    dv = acc - mean;
    red[t] = dv * dv; __syncthreads();
    for (int o = 32; o; o >>= 1) { if (t < o) red[t] += red[t + o]; __syncthreads(); }
    inv = rsqrtf(red[0] * (1.f / 64.f) + 1e-5f); __syncthreads();
    float o2 = fmaxf(dv * inv * g4[t] + be4[t], 0.f);

    red[t] = o2 * Wc3[t]; __syncthreads();
    for (int o = 32; o; o >>= 1) { if (t < o) red[t] += red[t + o]; __syncthreads(); }
    if (t == 0) out[g] = red[0] + bc3[0];
}

extern "C" void kernel_launch(void* const* d_in, const int* in_sizes, int n_in,
                              void* d_out, int out_size) {
    const float* h   = (const float*)d_in[0];
    const int*   src = (const int*)  d_in[1];
    const int*   dst = (const int*)  d_in[2];
    const int*   gid = (const int*)  d_in[3];
    const float* W1  = (const float*)d_in[4];
    const float* b1  = (const float*)d_in[5];
    const float* W2  = (const float*)d_in[6];
    const float* b2  = (const float*)d_in[7];
    const float* g1  = (const float*)d_in[8];
    const float* be1 = (const float*)d_in[9];
    const float* g2  = (const float*)d_in[10];
    const float* be2 = (const float*)d_in[11];
    const float* g3  = (const float*)d_in[12];
    const float* be3 = (const float*)d_in[13];
    const float* g4  = (const float*)d_in[14];
    const float* be4 = (const float*)d_in[15];
    const float* Wc1 = (const float*)d_in[16];
    const float* bc1 = (const float*)d_in[17];
    const float* Wc2 = (const float*)d_in[18];
    const float* bc2 = (const float*)d_in[19];
    const float* Wc3 = (const float*)d_in[20];
    const float* bc3 = (const float*)d_in[21];
    float* out = (float*)d_out;

    __half2* xh = nullptr; __half2* h1h = nullptr;
    cudaGetSymbolAddress((void**)&xh,  g_xh);
    cudaGetSymbolAddress((void**)&h1h, g_h1h);

    k_zero<<<(NN + 255) / 256, 256>>>();
    k_deg <<<(NE / 4 + 255) / 256, 256>>>((const int4*)src, (const int4*)dst);
    k_norm<<<(NN + 255) / 256, 256>>>();
    k_fill<<<(NE / 4 + 255) / 256, 256>>>((const int4*)src, (const int4*)dst);
    k_prep<<<(NN * 16 + 255) / 256, 256>>>(h);

    k_conv<<<(NN + 63) / 64, 256>>>(xh,  0, W1, b1, g1, be1);
    k_conv<<<(NN + 63) / 64, 256>>>(h1h, 1, W2, b2, g2, be2);

    k_pool<<<NG, 256>>>(gid);
    k_cls <<<NG, 64>>>(Wc1, bc1, g3, be3, Wc2, bc2, g4, be4, Wc3, bc3, out);
}